// round 6
// baseline (speedup 1.0000x reference)
#include <cuda_runtime.h>
#include <cstdint>

// Elman RNN split into (A) parallel precompute of u = x@W_ih^T + b_ih + b_hh
// over all (n,t), and (B) serial recurrence h_{t+1} = tanh(u_t + h_t@W_hh^T).
// N=2048, T=512, I=32, H=64, O=1.
// B: warp-per-sample (2048 warps, 3.46/SMSP), lane l owns units (2l,2l+1),
// W_hh in 128 regs, h double-buffered in smem, u prefetched 2 steps ahead.

#define TT 512
#define NN 2048

typedef unsigned long long ull;

__device__ float g_u[(size_t)NN * TT * 64];   // 268 MB scratch

__device__ __forceinline__ float tanh_acc(float s) {
    float e = __expf(2.0f * s);
    return 1.0f - __fdividef(2.0f, e + 1.0f);
}

// ---------------- Kernel A: u[n][t][j] = b_ih[j]+b_hh[j] + x[n,t,:].W_ih[j,:] ----------------
// grid = 2048 (block = sample), block = 256 threads: j = tid&63, t-group = tid>>6
__global__ void __launch_bounds__(256) precompute_u_kernel(
    const float* __restrict__ x,      // [N, T, I]
    const float* __restrict__ W_ih,   // [H, I]
    const float* __restrict__ b_ih,   // [H]
    const float* __restrict__ b_hh)   // [H]
{
    const int n  = blockIdx.x;
    const int j  = threadIdx.x & 63;
    const int tg = threadIdx.x >> 6;

    // W_ih row j as 16 f32x2 pairs in registers
    ull W[16];
    const ull* wp = reinterpret_cast<const ull*>(W_ih + j * 32);
    #pragma unroll
    for (int k = 0; k < 16; k++) W[k] = __ldg(wp + k);
    const float bias = __ldg(b_ih + j) + __ldg(b_hh + j);

    const float* xb = x + (size_t)n * TT * 32;
    float* ub = g_u + (size_t)n * TT * 64;

    for (int t = tg; t < TT; t += 4) {
        const float4* xr = reinterpret_cast<const float4*>(xb + t * 32);
        ull a0 = 0ull, a1 = 0ull;
        #pragma unroll
        for (int q = 0; q < 8; q++) {
            const float4 v = __ldg(xr + q);   // L1-broadcast across the 64 threads of this row
            ull lo, hi;
            asm("mov.b64 %0, {%1, %2};" : "=l"(lo) : "f"(v.x), "f"(v.y));
            asm("mov.b64 %0, {%1, %2};" : "=l"(hi) : "f"(v.z), "f"(v.w));
            asm("fma.rn.f32x2 %0, %1, %2, %0;" : "+l"(a0) : "l"(lo), "l"(W[2 * q]));
            asm("fma.rn.f32x2 %0, %1, %2, %0;" : "+l"(a1) : "l"(hi), "l"(W[2 * q + 1]));
        }
        asm("add.rn.f32x2 %0, %0, %1;" : "+l"(a0) : "l"(a1));
        float rx, ry;
        asm("mov.b64 {%0, %1}, %2;" : "=f"(rx), "=f"(ry) : "l"(a0));
        ub[t * 64 + j] = bias + rx + ry;      // coalesced 256B per row-group
    }
}

// ---------------- Kernel B: serial recurrence, warp-per-sample ----------------
__global__ void __launch_bounds__(32, 12) rnn_rec_kernel(
    const float* __restrict__ W_hh,   // [H, H]
    const float* __restrict__ fc_w,   // [1, H]
    const float* __restrict__ fc_b,   // [1]
    float* __restrict__ out)          // [N, 1]
{
    __shared__ __align__(16) float buf[2][64];   // double-buffered h

    const int l  = threadIdx.x;
    const int n  = blockIdx.x;
    const int u0 = 2 * l;
    const int u1 = u0 + 1;

    // W_hh rows for this lane's 2 units: 64 ull = 128 regs
    ull W0[32], W1[32];
    {
        const ull* p0 = reinterpret_cast<const ull*>(W_hh + u0 * 64);
        const ull* p1 = reinterpret_cast<const ull*>(W_hh + u1 * 64);
        #pragma unroll
        for (int k = 0; k < 32; k++) { W0[k] = __ldg(p0 + k); W1[k] = __ldg(p1 + k); }
    }

    // u stream for this lane: float2 (units u0,u1), stride 32 float2 per step
    const float2* up = reinterpret_cast<const float2*>(g_u + (size_t)n * TT * 64) + l;

    // init h0 = ones
    *reinterpret_cast<float2*>(&buf[0][u0]) = make_float2(1.0f, 1.0f);
    __syncwarp();

    // prefetch u_0, u_1 (distance-2 pipeline)
    float2 uc = __ldg(up);
    float2 un = __ldg(up + 32);

    float h0 = 1.0f, h1 = 1.0f;

    for (int t = 0; t < TT; t++) {
        const int cur = t & 1;
        const int nxt = cur ^ 1;

        // prefetch u_{t+2}
        const float2 u2 = (t + 2 < TT) ? __ldg(up + (t + 2) * 32) : make_float2(0.f, 0.f);

        const ulonglong2* vp = reinterpret_cast<const ulonglong2*>(&buf[cur][0]);

        // 4 chains: (unit0,unit1) x (lo,hi); seeds carry u_t
        float2 s0 = make_float2(uc.x, 0.0f);
        float2 s1 = make_float2(uc.y, 0.0f);
        ull a0 = *reinterpret_cast<ull*>(&s0);
        ull a1 = *reinterpret_cast<ull*>(&s1);
        ull c0 = 0ull, c1 = 0ull;

        #pragma unroll
        for (int g = 0; g < 16; g++) {
            const ulonglong2 v = vp[g];
            asm("fma.rn.f32x2 %0, %1, %2, %0;" : "+l"(a0) : "l"(v.x), "l"(W0[2 * g]));
            asm("fma.rn.f32x2 %0, %1, %2, %0;" : "+l"(a1) : "l"(v.x), "l"(W1[2 * g]));
            asm("fma.rn.f32x2 %0, %1, %2, %0;" : "+l"(c0) : "l"(v.y), "l"(W0[2 * g + 1]));
            asm("fma.rn.f32x2 %0, %1, %2, %0;" : "+l"(c1) : "l"(v.y), "l"(W1[2 * g + 1]));
        }

        asm("add.rn.f32x2 %0, %0, %1;" : "+l"(a0) : "l"(c0));
        asm("add.rn.f32x2 %0, %0, %1;" : "+l"(a1) : "l"(c1));
        float r0x, r0y, r1x, r1y;
        asm("mov.b64 {%0, %1}, %2;" : "=f"(r0x), "=f"(r0y) : "l"(a0));
        asm("mov.b64 {%0, %1}, %2;" : "=f"(r1x), "=f"(r1y) : "l"(a1));

        h0 = tanh_acc(r0x + r0y);
        h1 = tanh_acc(r1x + r1y);

        *reinterpret_cast<float2*>(&buf[nxt][u0]) = make_float2(h0, h1);
        __syncwarp();

        uc = un; un = u2;   // rotate u pipeline
    }

    // output head: sigmoid(h . fc_w + fc_b)
    float p = h0 * fc_w[u0] + h1 * fc_w[u1];
    #pragma unroll
    for (int o = 16; o; o >>= 1) p += __shfl_xor_sync(0xffffffffu, p, o);
    if (l == 0)
        out[n] = __fdividef(1.0f, 1.0f + __expf(-(p + fc_b[0])));
}

extern "C" void kernel_launch(void* const* d_in, const int* in_sizes, int n_in,
                              void* d_out, int out_size) {
    const float* x    = (const float*)d_in[0];
    const float* W_ih = (const float*)d_in[1];
    const float* W_hh = (const float*)d_in[2];
    const float* b_ih = (const float*)d_in[3];
    const float* b_hh = (const float*)d_in[4];
    const float* fc_w = (const float*)d_in[5];
    const float* fc_b = (const float*)d_in[6];
    float* out = (float*)d_out;

    precompute_u_kernel<<<NN, 256>>>(x, W_ih, b_ih, b_hh);
    rnn_rec_kernel<<<NN, 32>>>(W_hh, fc_w, fc_b, out);
}